// round 1
// baseline (speedup 1.0000x reference)
#include <cuda_runtime.h>
#include <math.h>

// ---------------------------------------------------------------------------
// VectorQuantizer: z[32,4096,64] fp32, codebook[1024,64] fp32
// Outputs (concatenated float32, reference return order):
//   quantized_st [8388608], loss [1], indices [131072], codebook_loss [1],
//   commitment_loss [1], perplexity [1], usage [1024], soft_usage [1024]
// ---------------------------------------------------------------------------

#define N_ROWS 131072
#define DIM    64
#define NCODES 1024
#define CHUNK  128

#define OFF_Q     0
#define OFF_LOSS  8388608
#define OFF_IDX   8388609
#define OFF_CBL   8519681
#define OFF_CML   8519682
#define OFF_PERP  8519683
#define OFF_USAGE 8519684
#define OFF_SOFT  8520708

// Scratch (device globals: no allocations allowed in kernel_launch).
__device__ float g_dist[(size_t)N_ROWS * NCODES];   // 512 MB distance matrix
__device__ float g_row_m[N_ROWS];                   // per-row min distance
__device__ float g_row_Z[N_ROWS];                   // per-row softmax denom (rel. to m)
__device__ int   g_row_idx[N_ROWS];                 // per-row argmin
__device__ float g_cc[NCODES];                      // ||codebook[c]||^2
__device__ float g_soft[NCODES];                    // soft usage accumulators
__device__ float g_counts[NCODES];                  // hard counts
__device__ float g_sq;                              // sum of squared (q - z)

__device__ __forceinline__ float ex2_approx(float x) {
    float y;
    asm("ex2.approx.ftz.f32 %0, %1;" : "=f"(y) : "f"(x));
    return y;
}

// ---------------------------------------------------------------------------
// k0: zero accumulators, precompute ||c||^2.  grid = 4 x 256 (1024 threads)
// ---------------------------------------------------------------------------
__global__ void k0_init(const float* __restrict__ cbk) {
    const int c = blockIdx.x * 256 + threadIdx.x;   // 0..1023
    const float4* p = reinterpret_cast<const float4*>(cbk + (size_t)c * DIM);
    float s = 0.f;
#pragma unroll
    for (int i = 0; i < 16; i++) {
        float4 v = p[i];
        s += v.x * v.x + v.y * v.y + v.z * v.z + v.w * v.w;
    }
    g_cc[c] = s;
    g_soft[c] = 0.f;
    g_counts[c] = 0.f;
    if (c == 0) g_sq = 0.f;
}

// ---------------------------------------------------------------------------
// k1: per-row distance GEMM + online (min, argmin, Z).  One thread per row.
//     z-row lives in 64 registers; codebook streamed through smem in chunks.
//     Distances written to g_dist for pass 2.
// grid = N_ROWS/256 x 256
// ---------------------------------------------------------------------------
__global__ void __launch_bounds__(256, 2) k1_gemm(const float* __restrict__ z,
                                                  const float* __restrict__ cbk) {
    __shared__ float  cc_s[NCODES];
    __shared__ float4 cb_s[CHUNK * 16];   // 128 codes x 64 floats = 32 KB

    const int tid = threadIdx.x;
    const int row = blockIdx.x * 256 + tid;

    for (int i = tid; i < NCODES; i += 256) cc_s[i] = g_cc[i];

    // Load z row into registers; accumulate ||z||^2.
    float zr[64];
    float zz = 0.f;
    const float4* zp = reinterpret_cast<const float4*>(z + (size_t)row * DIM);
#pragma unroll
    for (int i = 0; i < 16; i++) {
        float4 v = zp[i];
        zr[4 * i + 0] = v.x; zr[4 * i + 1] = v.y;
        zr[4 * i + 2] = v.z; zr[4 * i + 3] = v.w;
        zz += v.x * v.x + v.y * v.y + v.z * v.z + v.w * v.w;
    }

    float m = 3.402823466e38f;
    float Z = 0.f;
    int best = 0;
    float* drow = g_dist + (size_t)row * NCODES;

    for (int base = 0; base < NCODES; base += CHUNK) {
        __syncthreads();
        const float4* src = reinterpret_cast<const float4*>(cbk + (size_t)base * DIM);
        for (int i = tid; i < CHUNK * 16; i += 256) cb_s[i] = src[i];
        __syncthreads();

#pragma unroll 1
        for (int c = 0; c < CHUNK; c += 4) {
            float d[4];
#pragma unroll
            for (int j = 0; j < 4; j++) {
                const float4* cp = cb_s + (c + j) * 16;
                float a0 = 0.f, a1 = 0.f, a2 = 0.f, a3 = 0.f;
#pragma unroll
                for (int i = 0; i < 16; i++) {
                    float4 v = cp[i];
                    a0 = fmaf(zr[4 * i + 0], v.x, a0);
                    a1 = fmaf(zr[4 * i + 1], v.y, a1);
                    a2 = fmaf(zr[4 * i + 2], v.z, a2);
                    a3 = fmaf(zr[4 * i + 3], v.w, a3);
                }
                float dot = (a0 + a1) + (a2 + a3);
                d[j] = fmaf(-2.f, dot, zz + cc_s[base + c + j]);
            }
            *reinterpret_cast<float4*>(drow + base + c) =
                make_float4(d[0], d[1], d[2], d[3]);

            // Online softmax state: Z = sum exp(m - d_i), m = running min dist.
#pragma unroll
            for (int j = 0; j < 4; j++) {
                float t = m - d[j];
                float e = __expf(t > 0.f ? -t : t);   // exp(-|m - d|)
                if (d[j] < m) {
                    Z = fmaf(Z, e, 1.f);
                    m = d[j];
                    best = base + c + j;
                } else {
                    Z += e;
                }
            }
        }
    }
    g_row_m[row] = m;
    g_row_Z[row] = Z;
    g_row_idx[row] = best;
}

// ---------------------------------------------------------------------------
// k2: soft_usage accumulation.  CTA covers 128 rows; thread t owns codes
//     [4t, 4t+4).  prob = exp2(fma(-d, log2e, a)) with a = m*log2e - log2(Z).
// grid = N_ROWS/128 x 256
// ---------------------------------------------------------------------------
#define ROWS2 128
__global__ void __launch_bounds__(256) k2_soft() {
    __shared__ float sa[ROWS2];
    const int tid  = threadIdx.x;
    const int row0 = blockIdx.x * ROWS2;
    const float L2E = 1.4426950408889634f;

    for (int i = tid; i < ROWS2; i += 256) {
        float mm = g_row_m[row0 + i];
        float ZZ = g_row_Z[row0 + i];
        sa[i] = fmaf(mm, L2E, -__log2f(ZZ));
    }
    __syncthreads();

    const int c0 = tid * 4;
    float acc0 = 0.f, acc1 = 0.f, acc2 = 0.f, acc3 = 0.f;
#pragma unroll 4
    for (int r = 0; r < ROWS2; r++) {
        const float a = sa[r];
        const float4 v = *reinterpret_cast<const float4*>(
            g_dist + (size_t)(row0 + r) * NCODES + c0);
        acc0 += ex2_approx(fmaf(-v.x, L2E, a));
        acc1 += ex2_approx(fmaf(-v.y, L2E, a));
        acc2 += ex2_approx(fmaf(-v.z, L2E, a));
        acc3 += ex2_approx(fmaf(-v.w, L2E, a));
    }
    atomicAdd(&g_soft[c0 + 0], acc0);
    atomicAdd(&g_soft[c0 + 1], acc1);
    atomicAdd(&g_soft[c0 + 2], acc2);
    atomicAdd(&g_soft[c0 + 3], acc3);
}

// ---------------------------------------------------------------------------
// k3: gather quantized output, mse accumulation, counts, index writes.
// grid = (N_ROWS*64)/256 x 256, one thread per output element.
// ---------------------------------------------------------------------------
__global__ void __launch_bounds__(256) k3_quant(const float* __restrict__ z,
                                                const float* __restrict__ cbk,
                                                float* __restrict__ out) {
    const int e   = blockIdx.x * 256 + threadIdx.x;
    const int row = e >> 6;
    const int k   = e & 63;
    const int idx = g_row_idx[row];
    const float q  = cbk[(size_t)idx * DIM + k];
    const float zv = z[e];
    out[OFF_Q + e] = q;      // quantized_st == quantized (value-wise)

    float diff = q - zv;
    float s = diff * diff;
#pragma unroll
    for (int o = 16; o > 0; o >>= 1) s += __shfl_xor_sync(0xFFFFFFFFu, s, o);

    __shared__ float ws[8];
    if ((threadIdx.x & 31) == 0) ws[threadIdx.x >> 5] = s;
    __syncthreads();
    if (threadIdx.x == 0) {
        float t = 0.f;
#pragma unroll
        for (int i = 0; i < 8; i++) t += ws[i];
        atomicAdd(&g_sq, t);
    }
    if (k == 0) {
        atomicAdd(&g_counts[idx], 1.f);
        out[OFF_IDX + row] = (float)idx;
    }
}

// ---------------------------------------------------------------------------
// k4: finalize scalars, usage, soft_usage, perplexity.  1 CTA x 1024.
// ---------------------------------------------------------------------------
__global__ void __launch_bounds__(1024) k4_fin(float* __restrict__ out) {
    const int c = threadIdx.x;
    const float invN = 1.f / (float)N_ROWS;

    float usage = g_counts[c] * invN;
    out[OFF_USAGE + c] = usage;
    out[OFF_SOFT + c]  = g_soft[c] * invN;

    float term = usage * logf(usage + 1e-8f);
#pragma unroll
    for (int o = 16; o > 0; o >>= 1) term += __shfl_xor_sync(0xFFFFFFFFu, term, o);

    __shared__ float red[32];
    if ((c & 31) == 0) red[c >> 5] = term;
    __syncthreads();
    if (c == 0) {
        float sum = 0.f;
#pragma unroll
        for (int i = 0; i < 32; i++) sum += red[i];
        float perp = expf(-sum);
        float mse  = g_sq / (float)((size_t)N_ROWS * DIM);
        out[OFF_LOSS] = mse * 1.25f;   // cb_loss + 0.25 * commitment (equal values)
        out[OFF_CBL]  = mse;
        out[OFF_CML]  = mse;
        out[OFF_PERP] = perp;
    }
}

// ---------------------------------------------------------------------------
extern "C" void kernel_launch(void* const* d_in, const int* in_sizes, int n_in,
                              void* d_out, int out_size) {
    const float* z   = (const float*)d_in[0];
    const float* cbk = (const float*)d_in[1];
    float* out = (float*)d_out;
    (void)in_sizes; (void)n_in; (void)out_size;

    k0_init<<<4, 256>>>(cbk);
    k1_gemm<<<N_ROWS / 256, 256>>>(z, cbk);
    k2_soft<<<N_ROWS / ROWS2, 256>>>();
    k3_quant<<<(N_ROWS * DIM) / 256, 256>>>(z, cbk, out);
    k4_fin<<<1, 1024>>>(out);
}

// round 4
// speedup vs baseline: 1.5118x; 1.5118x over previous
#include <cuda_runtime.h>
#include <math.h>
#include <float.h>
#include <stdint.h>

// ---------------------------------------------------------------------------
// VectorQuantizer: z[32,4096,64] fp32, codebook[1024,64] fp32
// Output (concat float32): quantized[8388608], loss, indices[131072],
//   codebook_loss, commitment_loss, perplexity, usage[1024], soft_usage[1024]
// k1 distance GEMM: mma.sync m16n8k8 tf32, 3xTF32 emulation.
// ---------------------------------------------------------------------------

#define N_ROWS 131072
#define DIM    64
#define NCODES 1024
#define MT     128
#define ASTRIDE 68
#define BSTRIDE 72
#define TAU    0.01f

#define OFF_Q     0
#define OFF_LOSS  8388608
#define OFF_IDX   8388609
#define OFF_CBL   8519681
#define OFF_CML   8519682
#define OFF_PERP  8519683
#define OFF_USAGE 8519684
#define OFF_SOFT  8520708

__device__ float g_dist[(size_t)N_ROWS * NCODES];   // 512 MB scratch
__device__ float g_cbhi[64 * NCODES];               // tf32-hi, [k][n]
__device__ float g_cblo[64 * NCODES];               // tf32-lo, [k][n]
__device__ float g_cc[NCODES];
__device__ int   g_row_idx[N_ROWS];
__device__ float g_soft[NCODES];
__device__ float g_counts[NCODES];
__device__ float g_sq;

__device__ __forceinline__ float tf32f(float x) {
    uint32_t u;
    asm("cvt.rna.tf32.f32 %0, %1;" : "=r"(u) : "f"(x));
    return __uint_as_float(u);
}
__device__ __forceinline__ uint32_t smem_u32(const void* p) {
    uint32_t a;
    asm("{ .reg .u64 t; cvta.to.shared.u64 t, %1; cvt.u32.u64 %0, t; }"
        : "=r"(a) : "l"(p));
    return a;
}
__device__ __forceinline__ void cp16(uint32_t dst, const void* src) {
    asm volatile("cp.async.cg.shared.global [%0], [%1], 16;"
                 :: "r"(dst), "l"(src) : "memory");
}
#define CP_COMMIT() asm volatile("cp.async.commit_group;" ::: "memory")
#define CP_WAIT1()  asm volatile("cp.async.wait_group 1;" ::: "memory")

#define MMA(d, a, b0_, b1_) \
    asm volatile("mma.sync.aligned.m16n8k8.row.col.f32.tf32.tf32.f32 " \
        "{%0,%1,%2,%3}, {%4,%5,%6,%7}, {%8,%9}, {%0,%1,%2,%3};" \
        : "+f"((d)[0]), "+f"((d)[1]), "+f"((d)[2]), "+f"((d)[3]) \
        : "r"((a)[0]), "r"((a)[1]), "r"((a)[2]), "r"((a)[3]), \
          "r"(b0_), "r"(b1_))

// ---------------------------------------------------------------------------
// k0: transposed tf32 hi/lo codebook + cc + zero accumulators. 1024 threads.
// ---------------------------------------------------------------------------
__global__ void k0_init(const float* __restrict__ cbk) {
    const int c = blockIdx.x * 256 + threadIdx.x;
    float cs = 0.f;
#pragma unroll
    for (int k = 0; k < 64; k++) {
        float x = cbk[(size_t)c * 64 + k];
        cs = fmaf(x, x, cs);
        float hi = tf32f(x);
        g_cbhi[k * NCODES + c] = hi;
        g_cblo[k * NCODES + c] = tf32f(x - hi);
    }
    g_cc[c] = cs;
    g_soft[c] = 0.f;
    g_counts[c] = 0.f;
    if (c == 0) g_sq = 0.f;
}

// ---------------------------------------------------------------------------
// k1: distance GEMM -> g_dist. grid=1024 x 256thr. Warp = 16 rows x all codes.
// smem: bufs[2][9216] (B hi/lo chunks, dbl-buffered) + cc[1024] = 77824 B.
// A (128x68) staged in buffer 0 region first, extracted to registers.
// ---------------------------------------------------------------------------
__global__ void __launch_bounds__(256, 1) k1_gemm(const float* __restrict__ z) {
    extern __shared__ float sm1[];
    float* bufs = sm1;
    float* cc_s = sm1 + 18432;
    float* Ast  = sm1;                 // alias buffer 0 (8704 <= 9216 floats)
    const uint32_t smb = smem_u32(sm1);

    const int tid = threadIdx.x;
    const int w = tid >> 5, l = tid & 31;
    const int row0 = blockIdx.x * MT;

    // stage A (raw fp32) + cc
#pragma unroll
    for (int i = 0; i < 8; i++) {
        int id = tid + i * 256;
        int r = id >> 4, f4 = id & 15;
        float4 v = *reinterpret_cast<const float4*>(
            z + (size_t)(row0 + r) * DIM + f4 * 4);
        *reinterpret_cast<float4*>(&Ast[r * ASTRIDE + f4 * 4]) = v;
    }
    *reinterpret_cast<float4*>(&cc_s[tid * 4]) =
        *reinterpret_cast<const float4*>(g_cc + tid * 4);
    __syncthreads();

    // extract A fragments (tf32 hi/lo) + per-row zz
    uint32_t Ah[32], Al[32];
    const int rl = w * 16 + (l >> 2);
    float zz0 = 0.f, zz1 = 0.f;
#pragma unroll
    for (int kc = 0; kc < 8; kc++) {
        int kk = kc * 8 + (l & 3);
        float x0 = Ast[rl * ASTRIDE + kk];
        float x1 = Ast[(rl + 8) * ASTRIDE + kk];
        float x2 = Ast[rl * ASTRIDE + kk + 4];
        float x3 = Ast[(rl + 8) * ASTRIDE + kk + 4];
        zz0 = fmaf(x0, x0, fmaf(x2, x2, zz0));
        zz1 = fmaf(x1, x1, fmaf(x3, x3, zz1));
        float h;
        h = tf32f(x0); Ah[kc*4+0] = __float_as_uint(h); Al[kc*4+0] = __float_as_uint(tf32f(x0 - h));
        h = tf32f(x1); Ah[kc*4+1] = __float_as_uint(h); Al[kc*4+1] = __float_as_uint(tf32f(x1 - h));
        h = tf32f(x2); Ah[kc*4+2] = __float_as_uint(h); Al[kc*4+2] = __float_as_uint(tf32f(x2 - h));
        h = tf32f(x3); Ah[kc*4+3] = __float_as_uint(h); Al[kc*4+3] = __float_as_uint(tf32f(x3 - h));
    }
    zz0 += __shfl_xor_sync(0xFFFFFFFFu, zz0, 1);
    zz0 += __shfl_xor_sync(0xFFFFFFFFu, zz0, 2);
    zz1 += __shfl_xor_sync(0xFFFFFFFFu, zz1, 1);
    zz1 += __shfl_xor_sync(0xFFFFFFFFu, zz1, 2);
    __syncthreads();   // buffer 0 region free

    // prefetch chunk0 -> buf1, chunk1 -> buf0 (chunk ch -> buf (ch+1)&1)
#pragma unroll
    for (int p = 0; p < 2; p++) {
        const uint32_t boff = (uint32_t)(((p + 1) & 1) * 9216) * 4u;
        const int n0 = p * 64;
#pragma unroll
        for (int i = 0; i < 4; i++) {
            int id = tid + i * 256;
            int k = id >> 4, f4 = id & 15;
            uint32_t dst = smb + boff + (uint32_t)((k * BSTRIDE + f4 * 4) * 4);
            cp16(dst, g_cbhi + k * NCODES + n0 + f4 * 4);
            cp16(dst + 18432u, g_cblo + k * NCODES + n0 + f4 * 4);
        }
        CP_COMMIT();
    }

#pragma unroll 1
    for (int ch = 0; ch < 16; ch++) {
        CP_WAIT1();
        __syncthreads();
        const float* B = bufs + ((ch + 1) & 1) * 9216;

        float acc[32];
#pragma unroll
        for (int i = 0; i < 32; i++) acc[i] = 0.f;

#pragma unroll
        for (int kc = 0; kc < 8; kc++) {
            const uint32_t* ah = &Ah[kc * 4];
            const uint32_t* al = &Al[kc * 4];
            const int bb = (kc * 8 + (l & 3)) * BSTRIDE + (l >> 2);
#pragma unroll
            for (int s = 0; s < 8; s++) {
                uint32_t bh0 = __float_as_uint(B[bb + s * 8]);
                uint32_t bh1 = __float_as_uint(B[bb + s * 8 + 4 * BSTRIDE]);
                uint32_t bl0 = __float_as_uint(B[4608 + bb + s * 8]);
                uint32_t bl1 = __float_as_uint(B[4608 + bb + s * 8 + 4 * BSTRIDE]);
                MMA(&acc[s * 4], ah, bh0, bh1);
                MMA(&acc[s * 4], al, bh0, bh1);
                MMA(&acc[s * 4], ah, bl0, bl1);
            }
        }
        __syncthreads();   // all warps done reading this buffer

        if (ch < 14) {     // prefetch chunk ch+2 into the buffer just freed
            const int n0 = (ch + 2) * 64;
            const uint32_t boff = (uint32_t)(((ch + 1) & 1) * 9216) * 4u;
#pragma unroll
            for (int i = 0; i < 4; i++) {
                int id = tid + i * 256;
                int k = id >> 4, f4 = id & 15;
                uint32_t dst = smb + boff + (uint32_t)((k * BSTRIDE + f4 * 4) * 4);
                cp16(dst, g_cbhi + k * NCODES + n0 + f4 * 4);
                cp16(dst + 18432u, g_cblo + k * NCODES + n0 + f4 * 4);
            }
        }
        CP_COMMIT();

        // epilogue: d = zz + cc - 2*dot -> g_dist
        const int r0g = row0 + rl;
        const int colb = ch * 64 + 2 * (l & 3);
#pragma unroll
        for (int s = 0; s < 8; s++) {
            const int col = colb + s * 8;
            float2 cv = *reinterpret_cast<const float2*>(&cc_s[col]);
            float2 o0, o1;
            o0.x = fmaf(-2.f, acc[s*4+0], zz0 + cv.x);
            o0.y = fmaf(-2.f, acc[s*4+1], zz0 + cv.y);
            o1.x = fmaf(-2.f, acc[s*4+2], zz1 + cv.x);
            o1.y = fmaf(-2.f, acc[s*4+3], zz1 + cv.y);
            *reinterpret_cast<float2*>(g_dist + (size_t)r0g * NCODES + col) = o0;
            *reinterpret_cast<float2*>(g_dist + (size_t)(r0g + 8) * NCODES + col) = o1;
        }
    }
}

// ---------------------------------------------------------------------------
// k2: argmin(top-2 + exact fp32 refine) + Z + soft_usage + counts + indices.
//     warp-per-row, 128 rows/CTA, grid = 1024.
// ---------------------------------------------------------------------------
__global__ void __launch_bounds__(256) k2_fuse(const float* __restrict__ z,
                                               const float* __restrict__ cbk,
                                               float* __restrict__ out) {
    __shared__ float soft_s[NCODES];
    const int tid = threadIdx.x, w = tid >> 5, lane = tid & 31;
    for (int i = tid; i < NCODES; i += 256) soft_s[i] = 0.f;
    __syncthreads();

    float acc[32];
#pragma unroll
    for (int i = 0; i < 32; i++) acc[i] = 0.f;

    const int row0 = blockIdx.x * 128;
#pragma unroll 1
    for (int rr = 0; rr < 16; rr++) {
        const int row = row0 + w * 16 + rr;
        const float4* dr = reinterpret_cast<const float4*>(g_dist + (size_t)row * NCODES);
        float d[32];
#pragma unroll
        for (int j = 0; j < 8; j++) {
            float4 v = dr[j * 32 + lane];
            d[4*j+0] = v.x; d[4*j+1] = v.y; d[4*j+2] = v.z; d[4*j+3] = v.w;
        }
        // per-thread top-2 (global col = (i>>2)*128 + lane*4 + (i&3))
        float m = FLT_MAX, m2 = FLT_MAX;
        int c1 = 0, c2 = 0;
#pragma unroll
        for (int i = 0; i < 32; i++) {
            int col = (i >> 2) * 128 + lane * 4 + (i & 3);
            if (d[i] < m || (d[i] == m && col < c1)) {
                m2 = m; c2 = c1; m = d[i]; c1 = col;
            } else if (d[i] < m2 || (d[i] == m2 && col < c2)) {
                m2 = d[i]; c2 = col;
            }
        }
        // warp merge of top-2 sets
#pragma unroll
        for (int o = 16; o > 0; o >>= 1) {
            float om  = __shfl_xor_sync(0xFFFFFFFFu, m,  o);
            float om2 = __shfl_xor_sync(0xFFFFFFFFu, m2, o);
            int   oc1 = __shfl_xor_sync(0xFFFFFFFFu, c1, o);
            int   oc2 = __shfl_xor_sync(0xFFFFFFFFu, c2, o);
            if (om < m || (om == m && oc1 < c1)) {
                // other's best wins; my best competes with other's second
                float lm = m; int lc = c1;
                m = om; c1 = oc1;
                if (lm < om2 || (lm == om2 && lc < oc2)) { m2 = lm; c2 = lc; }
                else { m2 = om2; c2 = oc2; }
            } else {
                if (om < m2 || (om == m2 && oc1 < c2)) { m2 = om; c2 = oc1; }
            }
        }
        // softmax Z and per-code prob accumulation
        float s = 0.f;
#pragma unroll
        for (int i = 0; i < 32; i++) { d[i] = __expf(m - d[i]); s += d[i]; }
#pragma unroll
        for (int o = 16; o > 0; o >>= 1) s += __shfl_xor_sync(0xFFFFFFFFu, s, o);
        const float invZ = __fdividef(1.f, s);
#pragma unroll
        for (int i = 0; i < 32; i++) acc[i] = fmaf(d[i], invZ, acc[i]);

        // exact fp32 refine for near-ties (whole warp cooperates)
        int bc = c1;
        if (m2 - m < TAU) {
            float2 zv = *reinterpret_cast<const float2*>(z + (size_t)row * DIM + 2 * lane);
            float2 a  = *reinterpret_cast<const float2*>(cbk + (size_t)c1 * DIM + 2 * lane);
            float2 b  = *reinterpret_cast<const float2*>(cbk + (size_t)c2 * DIM + 2 * lane);
            float sA = a.x*a.x + a.y*a.y - 2.f*(zv.x*a.x + zv.y*a.y);
            float sB = b.x*b.x + b.y*b.y - 2.f*(zv.x*b.x + zv.y*b.y);
#pragma unroll
            for (int o = 16; o > 0; o >>= 1) {
                sA += __shfl_xor_sync(0xFFFFFFFFu, sA, o);
                sB += __shfl_xor_sync(0xFFFFFFFFu, sB, o);
            }
            if (sB < sA || (sB == sA && c2 < c1)) bc = c2;
        }
        if (lane == 0) {
            g_row_idx[row] = bc;
            out[OFF_IDX + row] = (float)bc;
            atomicAdd(&g_counts[bc], 1.f);
        }
    }
#pragma unroll
    for (int i = 0; i < 32; i++)
        atomicAdd(&soft_s[(i >> 2) * 128 + lane * 4 + (i & 3)], acc[i]);
    __syncthreads();
    for (int i = tid; i < NCODES; i += 256) atomicAdd(&g_soft[i], soft_s[i]);
}

// ---------------------------------------------------------------------------
// k3: gather quantized + mse.  One thread per float4.
// ---------------------------------------------------------------------------
__global__ void __launch_bounds__(256) k3_quant(const float* __restrict__ z,
                                                const float* __restrict__ cbk,
                                                float* __restrict__ out) {
    const int t = blockIdx.x * 256 + threadIdx.x;
    const int row = t >> 4, q = t & 15;
    const int idx = g_row_idx[row];
    float4 c = *reinterpret_cast<const float4*>(cbk + (size_t)idx * DIM + q * 4);
    float4 zv = *reinterpret_cast<const float4*>(z + (size_t)t * 4);
    *reinterpret_cast<float4*>(out + OFF_Q + (size_t)t * 4) = c;

    float dx = c.x - zv.x, dy = c.y - zv.y, dz = c.z - zv.z, dw = c.w - zv.w;
    float s = dx*dx + dy*dy + dz*dz + dw*dw;
#pragma unroll
    for (int o = 16; o > 0; o >>= 1) s += __shfl_xor_sync(0xFFFFFFFFu, s, o);

    __shared__ float ws[8];
    if ((threadIdx.x & 31) == 0) ws[threadIdx.x >> 5] = s;
    __syncthreads();
    if (threadIdx.x == 0) {
        float tt = 0.f;
#pragma unroll
        for (int i = 0; i < 8; i++) tt += ws[i];
        atomicAdd(&g_sq, tt);
    }
}

// ---------------------------------------------------------------------------
// k4: finalize scalars, usage, soft_usage, perplexity.
// ---------------------------------------------------------------------------
__global__ void __launch_bounds__(1024) k4_fin(float* __restrict__ out) {
    const int c = threadIdx.x;
    const float invN = 1.f / (float)N_ROWS;

    float usage = g_counts[c] * invN;
    out[OFF_USAGE + c] = usage;
    out[OFF_SOFT + c]  = g_soft[c] * invN;

    float term = usage * logf(usage + 1e-8f);
#pragma unroll
    for (int o = 16; o > 0; o >>= 1) term += __shfl_xor_sync(0xFFFFFFFFu, term, o);

    __shared__ float red[32];
    if ((c & 31) == 0) red[c >> 5] = term;
    __syncthreads();
    if (c == 0) {
        float sum = 0.f;
#pragma unroll
        for (int i = 0; i < 32; i++) sum += red[i];
        float mse = g_sq / (float)((size_t)N_ROWS * DIM);
        out[OFF_LOSS] = mse * 1.25f;
        out[OFF_CBL]  = mse;
        out[OFF_CML]  = mse;
        out[OFF_PERP] = expf(-sum);
    }
}

// ---------------------------------------------------------------------------
extern "C" void kernel_launch(void* const* d_in, const int* in_sizes, int n_in,
                              void* d_out, int out_size) {
    const float* z   = (const float*)d_in[0];
    const float* cbk = (const float*)d_in[1];
    float* out = (float*)d_out;
    (void)in_sizes; (void)n_in; (void)out_size;

    cudaFuncSetAttribute(k1_gemm, cudaFuncAttributeMaxDynamicSharedMemorySize, 77824);

    k0_init<<<4, 256>>>(cbk);
    k1_gemm<<<N_ROWS / MT, 256, 77824>>>(z);
    k2_fuse<<<N_ROWS / 128, 256>>>(z, cbk, out);
    k3_quant<<<(N_ROWS * DIM / 4) / 256, 256>>>(z, cbk, out);
    k4_fin<<<1, 1024>>>(out);
}

// round 6
// speedup vs baseline: 2.3603x; 1.5612x over previous
#include <cuda_runtime.h>
#include <cuda_bf16.h>
#include <cuda_fp16.h>
#include <math.h>
#include <float.h>
#include <stdint.h>

// ---------------------------------------------------------------------------
// VectorQuantizer: z[32,4096,64] fp32, codebook[1024,64] fp32
// Output (concat float32): quantized[8388608], loss, indices[131072],
//   codebook_loss, commitment_loss, perplexity, usage[1024], soft_usage[1024]
//
// k1: distance GEMM via mma.sync m16n8k16 bf16 (3-term hi/lo emulation),
//     stores fp16(d - chunk_min) + chunk mins.
// k2: Z/soft_usage from fp16 scratch + exact-fp32 argmin refine.
// ---------------------------------------------------------------------------

#define N_ROWS 131072
#define DIM    64
#define NCODES 1024
#define MT     128
#define BSTR   72
#define NCHUNK 16
#define L2E    1.4426950408889634f
#define CANDF  0.98019867f   /* exp(-0.02): candidate window */

#define OFF_Q     0
#define OFF_LOSS  8388608
#define OFF_IDX   8388609
#define OFF_CBL   8519681
#define OFF_CML   8519682
#define OFF_PERP  8519683
#define OFF_USAGE 8519684
#define OFF_SOFT  8520708

// Scratch (device globals; no allocations allowed).
__device__ uint32_t g_dh[(size_t)N_ROWS * 512];    // 256 MB: fp16x2 of (d - mch)
__device__ float    g_mch[NCHUNK * N_ROWS];        // per-chunk row mins
__device__ uint32_t g_cbhi[32 * NCODES];           // bf16x2-hi packed [k2][n]
__device__ uint32_t g_cblo[32 * NCODES];           // bf16x2-lo packed [k2][n]
__device__ float    g_cc[NCODES];
__device__ int      g_row_idx[N_ROWS];
__device__ float    g_soft[NCODES];
__device__ float    g_counts[NCODES];
__device__ float    g_sq;

// ---------------- helpers ---------------------------------------------------
__device__ __forceinline__ float ex2f(float x) {
    float y;
    asm("ex2.approx.ftz.f32 %0, %1;" : "=f"(y) : "f"(x));
    return y;
}
__device__ __forceinline__ uint32_t smem_u32(const void* p) {
    uint32_t a;
    asm("{ .reg .u64 t; cvta.to.shared.u64 t, %1; cvt.u32.u64 %0, t; }"
        : "=r"(a) : "l"(p));
    return a;
}
__device__ __forceinline__ void cp16(uint32_t dst, const void* src) {
    asm volatile("cp.async.cg.shared.global [%0], [%1], 16;"
                 :: "r"(dst), "l"(src) : "memory");
}
#define CP_COMMIT() asm volatile("cp.async.commit_group;" ::: "memory")
#define CP_WAIT1()  asm volatile("cp.async.wait_group 1;" ::: "memory")

__device__ __forceinline__ uint32_t pk_bf16x2(float a, float b) {
    // low half = a (even k), high half = b (odd k)
    __nv_bfloat16 ha = __float2bfloat16(a);
    __nv_bfloat16 hb = __float2bfloat16(b);
    return ((uint32_t)__bfloat16_as_ushort(hb) << 16) | __bfloat16_as_ushort(ha);
}
__device__ __forceinline__ float bf16_round(float a) {
    return __bfloat162float(__float2bfloat16(a));
}
__device__ __forceinline__ uint32_t pk_f16x2(float a, float b) {
    __half2 h = __floats2half2_rn(a, b);
    return *reinterpret_cast<uint32_t*>(&h);
}

#define MMAB(d, a, b0_, b1_) \
    asm volatile("mma.sync.aligned.m16n8k16.row.col.f32.bf16.bf16.f32 " \
        "{%0,%1,%2,%3}, {%4,%5,%6,%7}, {%8,%9}, {%0,%1,%2,%3};" \
        : "+f"((d)[0]), "+f"((d)[1]), "+f"((d)[2]), "+f"((d)[3]) \
        : "r"((a)[0]), "r"((a)[1]), "r"((a)[2]), "r"((a)[3]), \
          "r"(b0_), "r"(b1_))

// ---------------------------------------------------------------------------
// k0: packed bf16 hi/lo codebook (transposed [k2][n]) + cc + zero accums.
// ---------------------------------------------------------------------------
__global__ void k0_init(const float* __restrict__ cbk) {
    const int c = blockIdx.x * 256 + threadIdx.x;   // 0..1023
    float x[64];
    const float4* p = reinterpret_cast<const float4*>(cbk + (size_t)c * DIM);
    float cs = 0.f;
#pragma unroll
    for (int i = 0; i < 16; i++) {
        float4 v = p[i];
        x[4*i+0] = v.x; x[4*i+1] = v.y; x[4*i+2] = v.z; x[4*i+3] = v.w;
        cs = fmaf(v.x, v.x, fmaf(v.y, v.y, fmaf(v.z, v.z, fmaf(v.w, v.w, cs))));
    }
#pragma unroll
    for (int j = 0; j < 32; j++) {
        float a = x[2*j], b = x[2*j+1];
        float ha = bf16_round(a), hb = bf16_round(b);
        g_cbhi[j * NCODES + c] = pk_bf16x2(a, b);
        g_cblo[j * NCODES + c] = pk_bf16x2(a - ha, b - hb);
    }
    g_cc[c] = cs;
    g_soft[c] = 0.f;
    g_counts[c] = 0.f;
    if (c == 0) g_sq = 0.f;
}

// ---------------------------------------------------------------------------
// k1: bf16 3-term distance GEMM.  grid = 1024 x 256 thr, 2 CTAs/SM.
//     Warp = 16 rows x 1024 codes (16 chunks of 64).  Outputs fp16 d' + mins.
// ---------------------------------------------------------------------------
__global__ void __launch_bounds__(256, 2) k1_gemm(const float* __restrict__ z) {
    __shared__ uint32_t Bs[2][2][32 * BSTR];   // [buf][hi/lo][k2*BSTR + n]
    __shared__ float cc_s[NCODES];

    const int tid = threadIdx.x;
    const int w = tid >> 5, l = tid & 31, q = l & 3, nl = l >> 2;
    const int row0 = blockIdx.x * MT;

    // prefetch chunks 0,1 (chunk ch -> buffer ch&1)
#pragma unroll
    for (int p = 0; p < 2; p++) {
#pragma unroll
        for (int i = 0; i < 2; i++) {
            int id = tid + i * 256;
            int k2 = id >> 4, f4 = id & 15;
            cp16(smem_u32(&Bs[p][0][k2 * BSTR + f4 * 4]),
                 g_cbhi + k2 * NCODES + p * 64 + f4 * 4);
            cp16(smem_u32(&Bs[p][1][k2 * BSTR + f4 * 4]),
                 g_cblo + k2 * NCODES + p * 64 + f4 * 4);
        }
        CP_COMMIT();
    }
    *reinterpret_cast<float4*>(&cc_s[tid * 4]) =
        *reinterpret_cast<const float4*>(g_cc + tid * 4);

    // A fragments (bf16 hi/lo) directly from global + per-row zz
    uint32_t Ah[16], Al[16];
    float zz0 = 0.f, zz1 = 0.f;
    const int r0 = row0 + w * 16 + nl, r1 = r0 + 8;
#pragma unroll
    for (int kc = 0; kc < 4; kc++) {
        const int k = kc * 16 + 2 * q;
        float2 v0 = *reinterpret_cast<const float2*>(z + (size_t)r0 * DIM + k);
        float2 v1 = *reinterpret_cast<const float2*>(z + (size_t)r1 * DIM + k);
        float2 v2 = *reinterpret_cast<const float2*>(z + (size_t)r0 * DIM + k + 8);
        float2 v3 = *reinterpret_cast<const float2*>(z + (size_t)r1 * DIM + k + 8);
        zz0 = fmaf(v0.x, v0.x, fmaf(v0.y, v0.y, fmaf(v2.x, v2.x, fmaf(v2.y, v2.y, zz0))));
        zz1 = fmaf(v1.x, v1.x, fmaf(v1.y, v1.y, fmaf(v3.x, v3.x, fmaf(v3.y, v3.y, zz1))));
        float2 vv[4] = {v0, v1, v2, v3};
#pragma unroll
        for (int i = 0; i < 4; i++) {
            float hx = bf16_round(vv[i].x), hy = bf16_round(vv[i].y);
            Ah[kc * 4 + i] = pk_bf16x2(vv[i].x, vv[i].y);
            Al[kc * 4 + i] = pk_bf16x2(vv[i].x - hx, vv[i].y - hy);
        }
    }
    zz0 += __shfl_xor_sync(0xFFFFFFFFu, zz0, 1);
    zz0 += __shfl_xor_sync(0xFFFFFFFFu, zz0, 2);
    zz1 += __shfl_xor_sync(0xFFFFFFFFu, zz1, 1);
    zz1 += __shfl_xor_sync(0xFFFFFFFFu, zz1, 2);
    __syncthreads();

#pragma unroll 1
    for (int ch = 0; ch < NCHUNK; ch++) {
        CP_WAIT1();
        __syncthreads();
        const uint32_t* BH = Bs[ch & 1][0];
        const uint32_t* BL = Bs[ch & 1][1];

        float acc[32];
#pragma unroll
        for (int i = 0; i < 32; i++) acc[i] = 0.f;

#pragma unroll
        for (int kc = 0; kc < 4; kc++) {
            const uint32_t* ah = &Ah[kc * 4];
            const uint32_t* al = &Al[kc * 4];
            const int b0i = (kc * 8 + q) * BSTR + nl;
            const int b1i = (kc * 8 + q + 4) * BSTR + nl;
#pragma unroll
            for (int s = 0; s < 8; s++) {
                uint32_t bh0 = BH[b0i + s * 8];
                uint32_t bh1 = BH[b1i + s * 8];
                uint32_t bl0 = BL[b0i + s * 8];
                uint32_t bl1 = BL[b1i + s * 8];
                MMAB(&acc[s * 4], ah, bh0, bh1);
                MMAB(&acc[s * 4], al, bh0, bh1);
                MMAB(&acc[s * 4], ah, bl0, bl1);
            }
        }
        __syncthreads();

        if (ch < NCHUNK - 2) {
            const int n0 = (ch + 2) * 64;
#pragma unroll
            for (int i = 0; i < 2; i++) {
                int id = tid + i * 256;
                int k2 = id >> 4, f4 = id & 15;
                cp16(smem_u32(&Bs[ch & 1][0][k2 * BSTR + f4 * 4]),
                     g_cbhi + k2 * NCODES + n0 + f4 * 4);
                cp16(smem_u32(&Bs[ch & 1][1][k2 * BSTR + f4 * 4]),
                     g_cblo + k2 * NCODES + n0 + f4 * 4);
            }
        }
        CP_COMMIT();

        // epilogue: d = zz + cc - 2*dot; chunk mins; fp16(d - min) store
        float m0 = FLT_MAX, m1 = FLT_MAX;
#pragma unroll
        for (int s = 0; s < 8; s++) {
            float2 cv = *reinterpret_cast<const float2*>(&cc_s[ch * 64 + s * 8 + 2 * q]);
            acc[s*4+0] = fmaf(-2.f, acc[s*4+0], zz0 + cv.x);
            acc[s*4+1] = fmaf(-2.f, acc[s*4+1], zz0 + cv.y);
            acc[s*4+2] = fmaf(-2.f, acc[s*4+2], zz1 + cv.x);
            acc[s*4+3] = fmaf(-2.f, acc[s*4+3], zz1 + cv.y);
            m0 = fminf(m0, fminf(acc[s*4+0], acc[s*4+1]));
            m1 = fminf(m1, fminf(acc[s*4+2], acc[s*4+3]));
        }
        m0 = fminf(m0, __shfl_xor_sync(0xFFFFFFFFu, m0, 1));
        m0 = fminf(m0, __shfl_xor_sync(0xFFFFFFFFu, m0, 2));
        m1 = fminf(m1, __shfl_xor_sync(0xFFFFFFFFu, m1, 1));
        m1 = fminf(m1, __shfl_xor_sync(0xFFFFFFFFu, m1, 2));
        if (q == 0) {
            g_mch[ch * N_ROWS + r0] = m0;
            g_mch[ch * N_ROWS + r1] = m1;
        }
        uint32_t* o0 = g_dh + (size_t)r0 * 512 + ch * 32 + q;
        uint32_t* o1 = g_dh + (size_t)r1 * 512 + ch * 32 + q;
#pragma unroll
        for (int s = 0; s < 8; s++) {
            o0[s * 4] = pk_f16x2(acc[s*4+0] - m0, acc[s*4+1] - m0);
            o1[s * 4] = pk_f16x2(acc[s*4+2] - m1, acc[s*4+3] - m1);
        }
    }
}

// ---------------------------------------------------------------------------
// k2: Z + soft_usage + exact argmin refine + counts + index output.
//     warp-per-row (16 rows/warp), grid = 1024 x 256.
// ---------------------------------------------------------------------------
__global__ void __launch_bounds__(256) k2_fuse(const float* __restrict__ z,
                                               const float* __restrict__ cbk,
                                               float* __restrict__ out) {
    __shared__ float soft_s[NCODES];
    const int tid = threadIdx.x, w = tid >> 5, l = tid & 31;
    for (int i = tid; i < NCODES; i += 256) soft_s[i] = 0.f;
    __syncthreads();

    float soft_acc[32];
#pragma unroll
    for (int i = 0; i < 32; i++) soft_acc[i] = 0.f;

    const int rbase = blockIdx.x * 128 + w * 16;
#pragma unroll 1
    for (int rr = 0; rr < 16; rr++) {
        const int row = rbase + rr;
        // row min from chunk mins; per-chunk bias
        float mch = (l < NCHUNK) ? g_mch[l * N_ROWS + row] : FLT_MAX;
        float m = mch;
#pragma unroll
        for (int o = 16; o > 0; o >>= 1) m = fminf(m, __shfl_xor_sync(0xFFFFFFFFu, m, o));
        const float bias = (m - mch) * L2E;

        const uint4* rp = reinterpret_cast<const uint4*>(g_dh + (size_t)row * 512);
        const float2 zrow = *reinterpret_cast<const float2*>(z + (size_t)row * DIM + 2 * l);

        float e[32];
        float Z = 0.f, lemax = 0.f;
#pragma unroll
        for (int t = 0; t < 4; t++) {
            uint4 uq = rp[l + 32 * t];
            float b = __shfl_sync(0xFFFFFFFFu, bias, (l + 32 * t) >> 3);
            uint32_t us[4] = {uq.x, uq.y, uq.z, uq.w};
#pragma unroll
            for (int p = 0; p < 4; p++) {
                __half2 h = *reinterpret_cast<__half2*>(&us[p]);
                float2 dd = __half22float2(h);
                float e0 = ex2f(fmaf(-dd.x, L2E, b));
                float e1 = ex2f(fmaf(-dd.y, L2E, b));
                e[t * 8 + p * 2 + 0] = e0;
                e[t * 8 + p * 2 + 1] = e1;
                Z += e0 + e1;
                lemax = fmaxf(lemax, fmaxf(e0, e1));
            }
        }
        float emax = lemax;
#pragma unroll
        for (int o = 16; o > 0; o >>= 1) {
            Z += __shfl_xor_sync(0xFFFFFFFFu, Z, o);
            emax = fmaxf(emax, __shfl_xor_sync(0xFFFFFFFFu, emax, o));
        }
        const float invZ = __fdividef(1.f, Z);
#pragma unroll
        for (int i = 0; i < 32; i++) soft_acc[i] = fmaf(e[i], invZ, soft_acc[i]);

        // exact refine over all candidates within the window
        const float thr = emax * CANDF;
        float bd = FLT_MAX;
        int bc = 0x7FFFFFFF;
        unsigned bal = __ballot_sync(0xFFFFFFFFu, lemax >= thr);
        while (bal) {
            const int src = __ffs(bal) - 1;
            bal &= bal - 1;
#pragma unroll
            for (int jj = 0; jj < 32; jj++) {
                float ev = __shfl_sync(0xFFFFFFFFu, e[jj], src);
                if (ev >= thr) {
                    const int col = 8 * src + 256 * (jj >> 3) + (jj & 7);
                    float2 cv = *reinterpret_cast<const float2*>(
                        cbk + (size_t)col * DIM + 2 * l);
                    float s = fmaf(cv.x, cv.x, cv.y * cv.y)
                            - 2.f * fmaf(zrow.x, cv.x, zrow.y * cv.y);
#pragma unroll
                    for (int o = 16; o > 0; o >>= 1)
                        s += __shfl_xor_sync(0xFFFFFFFFu, s, o);
                    if (s < bd || (s == bd && col < bc)) { bd = s; bc = col; }
                }
            }
        }
        if (l == 0) {
            g_row_idx[row] = bc;
            out[OFF_IDX + row] = (float)bc;
            atomicAdd(&g_counts[bc], 1.f);
        }
    }
#pragma unroll
    for (int jj = 0; jj < 32; jj++)
        atomicAdd(&soft_s[8 * l + 256 * (jj >> 3) + (jj & 7)], soft_acc[jj]);
    __syncthreads();
    for (int i = tid; i < NCODES; i += 256) atomicAdd(&g_soft[i], soft_s[i]);
}

// ---------------------------------------------------------------------------
// k3: gather quantized + mse.  One thread per float4.
// ---------------------------------------------------------------------------
__global__ void __launch_bounds__(256) k3_quant(const float* __restrict__ z,
                                                const float* __restrict__ cbk,
                                                float* __restrict__ out) {
    const int t = blockIdx.x * 256 + threadIdx.x;
    const int row = t >> 4, q = t & 15;
    const int idx = g_row_idx[row];
    float4 c = *reinterpret_cast<const float4*>(cbk + (size_t)idx * DIM + q * 4);
    float4 zv = *reinterpret_cast<const float4*>(z + (size_t)t * 4);
    *reinterpret_cast<float4*>(out + OFF_Q + (size_t)t * 4) = c;

    float dx = c.x - zv.x, dy = c.y - zv.y, dz = c.z - zv.z, dw = c.w - zv.w;
    float s = dx*dx + dy*dy + dz*dz + dw*dw;
#pragma unroll
    for (int o = 16; o > 0; o >>= 1) s += __shfl_xor_sync(0xFFFFFFFFu, s, o);

    __shared__ float ws[8];
    if ((threadIdx.x & 31) == 0) ws[threadIdx.x >> 5] = s;
    __syncthreads();
    if (threadIdx.x == 0) {
        float tt = 0.f;
#pragma unroll
        for (int i = 0; i < 8; i++) tt += ws[i];
        atomicAdd(&g_sq, tt);
    }
}

// ---------------------------------------------------------------------------
// k4: finalize scalars, usage, soft_usage, perplexity.
// ---------------------------------------------------------------------------
__global__ void __launch_bounds__(1024) k4_fin(float* __restrict__ out) {
    const int c = threadIdx.x;
    const float invN = 1.f / (float)N_ROWS;

    float usage = g_counts[c] * invN;
    out[OFF_USAGE + c] = usage;
    out[OFF_SOFT + c]  = g_soft[c] * invN;

    float term = usage * logf(usage + 1e-8f);
#pragma unroll
    for (int o = 16; o > 0; o >>= 1) term += __shfl_xor_sync(0xFFFFFFFFu, term, o);

    __shared__ float red[32];
    if ((c & 31) == 0) red[c >> 5] = term;
    __syncthreads();
    if (c == 0) {
        float sum = 0.f;
#pragma unroll
        for (int i = 0; i < 32; i++) sum += red[i];
        float mse = g_sq / (float)((size_t)N_ROWS * DIM);
        out[OFF_LOSS] = mse * 1.25f;
        out[OFF_CBL]  = mse;
        out[OFF_CML]  = mse;
        out[OFF_PERP] = expf(-sum);
    }
}

// ---------------------------------------------------------------------------
extern "C" void kernel_launch(void* const* d_in, const int* in_sizes, int n_in,
                              void* d_out, int out_size) {
    const float* z   = (const float*)d_in[0];
    const float* cbk = (const float*)d_in[1];
    float* out = (float*)d_out;
    (void)in_sizes; (void)n_in; (void)out_size;

    k0_init<<<4, 256>>>(cbk);
    k1_gemm<<<N_ROWS / MT, 256>>>(z);
    k2_fuse<<<N_ROWS / 128, 256>>>(z, cbk, out);
    k3_quant<<<(N_ROWS * DIM / 4) / 256, 256>>>(z, cbk, out);
    k4_fin<<<1, 1024>>>(out);
}